// round 2
// baseline (speedup 1.0000x reference)
#include <cuda_runtime.h>

#define IMG_H 768
#define IMG_W 768
#define HWSZ  (IMG_H*IMG_W)
#define BATCH 16
#define NTOT  (BATCH*HWSZ)
#define TILE  32
#define HALO  9
#define SWD   50          // TILE + 2*HALO
#define SP    53          // smem pitch (odd-ish -> conflict-free strided reads)
#define TP    33          // tmp pitch
#define NBINS 2048
#define CAP   (1<<17)

// ---------------- global scratch (no allocations allowed) ----------------
__device__ float  g_g3[19];
__device__ float  g_g1[7];
__device__ double g_acc[15];
// acc idx: 0 rc, 1 sum_in, 2 sum_pr, 3 ex, 4 ey, 5 tex, 6 lf, 7 mid, 8 hf,
//          9 syn, 10 ic, 11 nb, 12 ntex, 13 nf, 14 nfb
__device__ unsigned int g_hist[2*NBINS];   // [0]=yp(body), [1]=xi(body)
__device__ unsigned int g_cnt[8];
__device__ float        g_buf[8][CAP];
__device__ int          g_qbin[8];
__device__ unsigned int g_qrank[8];
__device__ float        g_qfrac[2];

// ---------------- init: zero accumulators, compute gauss weights ----------
__global__ void k_init() {
  int tid = threadIdx.x;
  for (int i = tid; i < 2*NBINS; i += blockDim.x) g_hist[i] = 0u;
  if (tid < 15) g_acc[tid] = 0.0;
  if (tid < 8) { g_cnt[tid] = 0u; g_qbin[tid] = -1; g_qrank[tid] = 0u; }
  if (tid == 0) {
    float g[19]; float s = 0.f;
    for (int i = 0; i < 19; i++) { float c = (float)(i - 9) / 3.0f; g[i] = expf(-0.5f*c*c); s += g[i]; }
    for (int i = 0; i < 19; i++) g_g3[i] = g[i] / s;
    float h[7]; s = 0.f;
    for (int i = 0; i < 7; i++) { float c = (float)(i - 3); h[i] = expf(-0.5f*c*c); s += h[i]; }
    for (int i = 0; i < 7; i++) g_g1[i] = h[i] / s;
    g_qfrac[0] = 0.f; g_qfrac[1] = 0.f;
  }
}

// ---------------- separable conv helpers (4-wide sliding windows) ---------
__device__ __forceinline__ void hpass19(const float* __restrict__ src,
                                        float* __restrict__ tmp,
                                        const float* __restrict__ w, int tid) {
  for (int i = tid; i < SWD*8; i += 256) {
    int r = i >> 3, cg = (i & 7) * 4;
    const float* row = src + r*SP + cg;
    float v[22];
    #pragma unroll
    for (int j = 0; j < 22; j++) v[j] = row[j];
    #pragma unroll
    for (int k = 0; k < 4; k++) {
      float a = 0.f;
      #pragma unroll
      for (int j = 0; j < 19; j++) a += w[j] * v[k+j];
      tmp[r*TP + cg + k] = a;
    }
  }
}
__device__ __forceinline__ void vpass19(const float* __restrict__ tmp,
                                        const float* __restrict__ w,
                                        int lx, int r0, float out[4]) {
  float v[22];
  #pragma unroll
  for (int j = 0; j < 22; j++) v[j] = tmp[(r0+j)*TP + lx];
  #pragma unroll
  for (int k = 0; k < 4; k++) {
    float a = 0.f;
    #pragma unroll
    for (int j = 0; j < 19; j++) a += w[j] * v[k+j];
    out[k] = a;
  }
}
__device__ __forceinline__ void hpass7(const float* __restrict__ src,
                                       float* __restrict__ tmp,
                                       const float* __restrict__ w, int tid) {
  for (int i = tid; i < SWD*8; i += 256) {
    int r = i >> 3, cg = (i & 7) * 4;
    const float* row = src + r*SP + cg + 6;
    float v[10];
    #pragma unroll
    for (int j = 0; j < 10; j++) v[j] = row[j];
    #pragma unroll
    for (int k = 0; k < 4; k++) {
      float a = 0.f;
      #pragma unroll
      for (int j = 0; j < 7; j++) a += w[j] * v[k+j];
      tmp[r*TP + cg + k] = a;
    }
  }
}
__device__ __forceinline__ void vpass7(const float* __restrict__ tmp,
                                       const float* __restrict__ w,
                                       int lx, int r0, float out[4]) {
  float v[10];
  #pragma unroll
  for (int j = 0; j < 10; j++) v[j] = tmp[(r0+6+j)*TP + lx];
  #pragma unroll
  for (int k = 0; k < 4; k++) {
    float a = 0.f;
    #pragma unroll
    for (int j = 0; j < 7; j++) a += w[j] * v[k+j];
    out[k] = a;
  }
}

__device__ __forceinline__ int binof(float x) {
  int b = (int)(x * (float)NBINS);
  return b < 0 ? 0 : (b > NBINS-1 ? NBINS-1 : b);
}

// ---------------- fused main kernel ---------------------------------------
__global__ __launch_bounds__(256) void k_main(
    const float* __restrict__ yp, const float* __restrict__ npred,
    const float* __restrict__ xi, const float* __restrict__ xm,
    const float* __restrict__ wt, const float* __restrict__ nsyn)
{
  extern __shared__ float sm[];
  float* s_xi  = sm;
  float* s_yp  = sm + SWD*SP;
  float* s_xm  = sm + 2*SWD*SP;
  float* s_tmp = sm + 3*SWD*SP;
  unsigned* s_hist = (unsigned*)(s_tmp + SWD*TP);
  float* s_w   = (float*)(s_hist + 2*NBINS);  // 19 + 7
  float* s_red = s_w + 26;                    // 8 warps * 15

  const int tid = threadIdx.x;
  const int b   = blockIdx.z;
  const int ty0 = blockIdx.y * TILE - HALO;
  const int tx0 = blockIdx.x * TILE - HALO;
  const unsigned ib = (unsigned)b * HWSZ;

  for (int i = tid; i < 2*NBINS; i += 256) s_hist[i] = 0u;
  if (tid < 19) s_w[tid] = g_g3[tid];
  else if (tid < 26) s_w[tid] = g_g1[tid - 19];

  // cooperative tile load (zero padding at image borders)
  for (int i = tid; i < SWD*SWD; i += 256) {
    int r = i / SWD, c = i - r*SWD;
    int gy = ty0 + r, gx = tx0 + c;
    float v1 = 0.f, v2 = 0.f, v3 = 0.f;
    if (gy >= 0 && gy < IMG_H && gx >= 0 && gx < IMG_W) {
      unsigned g = ib + (unsigned)gy*IMG_W + (unsigned)gx;
      v1 = xi[g]; v2 = yp[g]; v3 = xm[g];
    }
    int o = r*SP + c;
    s_xi[o] = v1; s_yp[o] = v2; s_xm[o] = v3;
  }
  __syncthreads();

  const int lx = tid & 31;
  const int r0 = (tid >> 5) * 4;   // this thread's 4 consecutive output rows

  float low_m[4], low_i[4], low_p[4], mid_i[4], mid_p[4];

  hpass19(s_xm, s_tmp, s_w, tid);  __syncthreads();
  vpass19(s_tmp, s_w, lx, r0, low_m); __syncthreads();
  hpass19(s_xi, s_tmp, s_w, tid);  __syncthreads();
  vpass19(s_tmp, s_w, lx, r0, low_i); __syncthreads();
  hpass19(s_yp, s_tmp, s_w, tid);  __syncthreads();
  vpass19(s_tmp, s_w, lx, r0, low_p); __syncthreads();
  hpass7 (s_xi, s_tmp, s_w+19, tid); __syncthreads();
  vpass7 (s_tmp, s_w+19, lx, r0, mid_i); __syncthreads();
  hpass7 (s_yp, s_tmp, s_w+19, tid); __syncthreads();
  vpass7 (s_tmp, s_w+19, lx, r0, mid_p);
  #pragma unroll
  for (int k = 0; k < 4; k++) { mid_i[k] -= low_i[k]; mid_p[k] -= low_p[k]; }

  // per-pixel accumulation
  float a_rc=0.f, a_in=0.f, a_pr=0.f, a_ex=0.f, a_ey=0.f, a_tex=0.f,
        a_lf=0.f, a_mid=0.f, a_hf=0.f, a_syn=0.f, a_ic=0.f;
  int c_nb=0, c_tex=0, c_nf=0, c_nfb=0;

  const int sx = lx + HALO;
  #pragma unroll
  for (int k = 0; k < 4; k++) {
    const int sy = r0 + k + HALO;
    const int gy = blockIdx.y*TILE + r0 + k;
    const int gx = blockIdx.x*TILE + lx;
    const unsigned g = ib + (unsigned)gy*IMG_W + (unsigned)gx;

    const float* ci = s_xi + sy*SP + sx;
    const float* cp = s_yp + sy*SP + sx;
    float i00=ci[-SP-1], i01=ci[-SP], i02=ci[-SP+1];
    float i10=ci[-1],    i11=ci[0],   i12=ci[1];
    float i20=ci[SP-1],  i21=ci[SP],  i22=ci[SP+1];
    float p00=cp[-SP-1], p01=cp[-SP], p02=cp[-SP+1];
    float p10=cp[-1],    p11=cp[0],   p12=cp[1];
    float p20=cp[SP-1],  p21=cp[SP],  p22=cp[SP+1];

    float wv = wt[g], nr = npred[g], ns = nsyn[g];
    a_rc += fabsf(p11*wv - i11*wv);

    bool body = (i11 > 0.15f) && (i11 < 0.85f);
    if (body) {
      c_nb++; a_in += i11; a_pr += p11;
      atomicAdd(&s_hist[binof(p11)], 1u);
      atomicAdd(&s_hist[NBINS + binof(i11)], 1u);
    }

    float gxi = (i02 - i00) + 2.f*(i12 - i10) + (i22 - i20);
    float gyi = (i20 - i00) + 2.f*(i21 - i01) + (i22 - i02);
    float gxp = (p02 - p00) + 2.f*(p12 - p10) + (p22 - p20);
    float gyp = (p20 - p00) + 2.f*(p21 - p01) + (p22 - p02);
    float lapi = i01 + i10 + i12 + i21 - 4.f*i11;
    float lapp = p01 + p10 + p12 + p21 - 4.f*p11;

    a_ex += fabsf(gxp - gxi);
    a_ey += fabsf(gyp - gyi);

    float gmi = sqrtf(gxi*gxi + gyi*gyi + 1e-8f);
    float gmp = sqrtf(gxp*gxp + gyp*gyp + 1e-8f);

    if (gmi > 0.03f && gmi < 0.5f) { c_tex++; a_tex += fabsf(gmp - gmi); }

    if (gmi < 0.03f) {  // flat
      c_nf++;
      a_hf += fabsf(fabsf(lapp) - 0.3f*fabsf(lapi));
      a_ic += fmaxf(gmp - 2.0f*gmi, 0.f);
      if (body) {
        c_nfb++;
        a_lf  += fabsf((low_p[k] - low_m[k]) - 0.3f*(low_i[k] - low_m[k]));
        a_mid += fabsf(fabsf(mid_p[k]) - 0.3f*fabsf(mid_i[k]));
        a_syn += fabsf(nr - ns);
      }
    }
  }

  // block reduction -> double atomics
  float red[15] = { a_rc, a_in, a_pr, a_ex, a_ey, a_tex, a_lf, a_mid, a_hf,
                    a_syn, a_ic, (float)c_nb, (float)c_tex, (float)c_nf, (float)c_nfb };
  int lane = tid & 31, warp = tid >> 5;
  #pragma unroll
  for (int q = 0; q < 15; q++) {
    float v = red[q];
    #pragma unroll
    for (int o = 16; o > 0; o >>= 1) v += __shfl_xor_sync(0xffffffffu, v, o);
    if (lane == 0) s_red[warp*15 + q] = v;
  }
  __syncthreads();
  if (tid < 15) {
    double s = 0.0;
    #pragma unroll
    for (int w2 = 0; w2 < 8; w2++) s += (double)s_red[w2*15 + tid];
    atomicAdd(&g_acc[tid], s);
  }
  // flush histograms
  for (int i = tid; i < 2*NBINS; i += 256) {
    unsigned v = s_hist[i];
    if (v) atomicAdd(&g_hist[i], v);
  }
}

// ---------------- scan: find target bins + local ranks --------------------
__global__ void k_scan() {
  __shared__ unsigned sh[NBINS];
  int tid = threadIdx.x;
  unsigned n = (unsigned)(g_acc[11] + 0.5);
  unsigned ranks[4];
  float fr[2];
  {
    float fn = (float)(n > 0 ? n - 1 : 0);
    for (int qi = 0; qi < 2; qi++) {
      float q = qi ? 0.75f : 0.25f;
      float pos = q * fn;
      float flo = floorf(pos), fhi = ceilf(pos);
      if (flo < 0.f) flo = 0.f; if (flo > (float)(NTOT-1)) flo = (float)(NTOT-1);
      if (fhi < 0.f) fhi = 0.f; if (fhi > (float)(NTOT-1)) fhi = (float)(NTOT-1);
      ranks[qi*2+0] = (unsigned)flo;
      ranks[qi*2+1] = (unsigned)fhi;
      fr[qi] = pos - flo;
    }
  }
  if (tid == 0) { g_qfrac[0] = fr[0]; g_qfrac[1] = fr[1]; }
  for (int arr = 0; arr < 2; arr++) {
    for (int i = tid; i < NBINS; i += blockDim.x) sh[i] = g_hist[arr*NBINS + i];
    __syncthreads();
    if (tid == 0) {
      unsigned cum = 0;
      for (int b = 0; b < NBINS; b++) {
        unsigned c = sh[b];
        #pragma unroll
        for (int j = 0; j < 4; j++) {
          unsigned r = ranks[j];
          if (r >= cum && r < cum + c) { g_qbin[arr*4+j] = b; g_qrank[arr*4+j] = r - cum; }
        }
        cum += c;
      }
    }
    __syncthreads();
  }
}

// ---------------- collect candidate values in target bins -----------------
__global__ void k_collect(const float* __restrict__ yp, const float* __restrict__ xi) {
  __shared__ int tb[8];
  if (threadIdx.x < 8) tb[threadIdx.x] = g_qbin[threadIdx.x];
  __syncthreads();
  for (unsigned i = blockIdx.x*blockDim.x + threadIdx.x; i < (unsigned)NTOT; i += gridDim.x*blockDim.x) {
    float x = xi[i];
    if (x > 0.15f && x < 0.85f) {
      float y = yp[i];
      int by = binof(y), bx = binof(x);
      #pragma unroll
      for (int t = 0; t < 4; t++)
        if (by == tb[t]) { unsigned p = atomicAdd(&g_cnt[t], 1u); if (p < CAP) g_buf[t][p] = y; }
      #pragma unroll
      for (int t = 4; t < 8; t++)
        if (bx == tb[t]) { unsigned p = atomicAdd(&g_cnt[t], 1u); if (p < CAP) g_buf[t][p] = x; }
    }
  }
}

// ---------------- final: exact radix select + combine ---------------------
__global__ void k_final(float* __restrict__ out) {
  __shared__ unsigned hist[256];
  __shared__ unsigned s_sel, s_r;
  __shared__ float s_vals[8];
  int tid = threadIdx.x;

  for (int t = 0; t < 8; t++) {
    unsigned n_t = min(g_cnt[t], (unsigned)CAP);
    int bin = g_qbin[t];
    unsigned r = g_qrank[t];
    if (bin < 0 || n_t == 0) { if (tid == 0) s_vals[t] = 0.f; __syncthreads(); continue; }
    unsigned prefix = 0;
    for (int round = 0; round < 4; round++) {
      int shift = 24 - 8*round;
      hist[tid] = 0u;
      __syncthreads();
      for (unsigned i = tid; i < n_t; i += 256) {
        unsigned u = __float_as_uint(g_buf[t][i]);   // values >= 0 -> bit order == float order
        bool ok = (round == 0) || ((u >> (shift + 8)) == prefix);
        if (ok) atomicAdd(&hist[(u >> shift) & 255u], 1u);
      }
      __syncthreads();
      if (tid == 0) {
        unsigned cum = 0; unsigned b = 0;
        for (; b < 256; b++) { unsigned c = hist[b]; if (r < cum + c) break; cum += c; }
        s_sel = b; s_r = r - cum;
      }
      __syncthreads();
      prefix = (prefix << 8) | s_sel;
      r = s_r;
      __syncthreads();
    }
    if (tid == 0) s_vals[t] = __uint_as_float(prefix);
    __syncthreads();
  }

  if (tid == 0) {
    const double N = (double)NTOT;
    double nb = g_acc[11], ntex = g_acc[12], nf = g_acc[13], nfb = g_acc[14];
    double rc = g_acc[0] / N;
    double dnb = nb > 1.0 ? nb : 1.0;
    double mean_in = g_acc[1] / dnb, mean_pr = g_acc[2] / dnb;

    float f0 = g_qfrac[0], f1 = g_qfrac[1];
    float q25p = s_vals[0]*(1.f-f0) + s_vals[1]*f0;
    float q75p = s_vals[2]*(1.f-f1) + s_vals[3]*f1;
    float q25i = s_vals[4]*(1.f-f0) + s_vals[5]*f0;
    float q75i = s_vals[6]*(1.f-f1) + s_vals[7]*f1;

    double dm  = mean_pr - mean_in;
    double d25 = (double)q25p - (double)q25i;
    double d75 = (double)q75p - (double)q75i;
    double hu  = dm*dm + 0.5*(d25*d25 + d75*d75);
    double loss_hu = (nb > 4096.0) ? hu : 0.0;

    double edge = g_acc[3]/N + g_acc[4]/N;
    double tex  = (ntex > 100.0) ? g_acc[5]/(ntex > 1.0 ? ntex : 1.0) : 0.0;
    double lf   = (nfb  > 100.0) ? g_acc[6]/(nfb  > 1.0 ? nfb  : 1.0) : 0.0;
    double mid  = (nfb  > 100.0) ? g_acc[7]/(nfb  > 1.0 ? nfb  : 1.0) : 0.0;
    double hf   = (nf   > 100.0) ? g_acc[8]/(nf   > 1.0 ? nf   : 1.0) : 0.0;
    double syn  = (nfb  > 100.0) ? g_acc[9]/(nfb  > 1.0 ? nfb  : 1.0) : 0.0;
    double ic   = (nf   > 100.0) ? g_acc[10]/(nf  > 1.0 ? nf   : 1.0) : 0.0;

    double total = 2.0*rc + 1.5*loss_hu + 1.0*edge + 0.8*tex
                 + 1.5*hf + 0.8*mid + 0.6*lf + 1.0*syn + 0.8*ic;
    out[0] = (float)total;
  }
}

// ---------------- launch ---------------------------------------------------
extern "C" void kernel_launch(void* const* d_in, const int* in_sizes, int n_in,
                              void* d_out, int out_size) {
  const float* yp    = (const float*)d_in[0];
  const float* npred = (const float*)d_in[1];
  const float* xi    = (const float*)d_in[2];
  // d_in[3] = x_ip1 : unused by the reference
  const float* xm    = (const float*)d_in[4];
  const float* wt    = (const float*)d_in[5];
  const float* nsyn  = (const float*)d_in[6];
  float* out = (float*)d_out;

  size_t smem = (size_t)(3*SWD*SP + SWD*TP) * 4   // tiles + tmp
              + (size_t)(2*NBINS) * 4              // hist
              + (size_t)(26 + 8*15) * 4;           // weights + reduction
  cudaFuncSetAttribute(k_main, cudaFuncAttributeMaxDynamicSharedMemorySize, (int)smem);

  k_init<<<1, 256>>>();
  dim3 grid(IMG_W/TILE, IMG_H/TILE, BATCH);
  k_main<<<grid, 256, smem>>>(yp, npred, xi, xm, wt, nsyn);
  k_scan<<<1, 256>>>();
  k_collect<<<1184, 256>>>(yp, xi);
  k_final<<<1, 256>>>(out);
}